// round 3
// baseline (speedup 1.0000x reference)
#include <cuda_runtime.h>
#include <math.h>

#define Bn 256
#define Mn 512
#define Dn 512
#define Cn 8
#define U1 512
#define U2 256
#define U3 128

// Scratch (no allocation allowed -> __device__ globals; referenced ONLY in
// device code — host-side references to __device__ symbols are invalid!)
__device__ float g_pooled[Bn * Dn];          // (B, D)
__device__ float g_h1[Cn * Bn * U1];         // (C, B, 512)
__device__ float g_h2[Cn * Bn * U2];         // (C, B, 256)
__device__ float g_term[Cn * Bn];            // per (c,b) loss term

// ---------------------------------------------------------------------------
// 1) Masked sum pooling: pooled[b,d] = sum_m ec[b,m,d] * (mask[b,m]==0)
// ---------------------------------------------------------------------------
__global__ void pool_kernel(const float* __restrict__ ec,
                            const float* __restrict__ mask) {
    const int b = blockIdx.x;
    const int dbase = blockIdx.y * 256;
    const int tid = threadIdx.x;

    __shared__ float keep[Mn];
    for (int i = tid; i < Mn; i += 256)
        keep[i] = (mask[b * Mn + i] == 0.0f) ? 1.0f : 0.0f;
    __syncthreads();

    const float* p = ec + ((size_t)b * Mn) * Dn + dbase + tid;
    float acc = 0.0f;
#pragma unroll 8
    for (int m = 0; m < Mn; m++)
        acc = fmaf(p[(size_t)m * Dn], keep[m], acc);

    g_pooled[b * Dn + dbase + tid] = acc;
}

// ---------------------------------------------------------------------------
// 2) Layers 1+2: 64x64 tile, K-step 32, 256 threads, 4x4 micro-tile,
//    register-prefetch double buffering. Scratch pointers selected in
//    device code via LAYER template param.
// ---------------------------------------------------------------------------
template <int LAYER>
__global__ __launch_bounds__(256) void gemm_relu_kernel(
        const float* __restrict__ W, const float* __restrict__ bias) {
    constexpr int K = (LAYER == 1) ? Dn : U1;
    constexpr int N = (LAYER == 1) ? U1 : U2;
    constexpr bool AHASC = (LAYER != 1);
    const float* Aroot = (LAYER == 1) ? g_pooled : g_h1;
    float* Oroot       = (LAYER == 1) ? g_h1     : g_h2;

    const int c  = blockIdx.z;
    const int b0 = blockIdx.y * 64;
    const int n0 = blockIdx.x * 64;
    const int tid = threadIdx.x;
    const int tb = tid >> 4;       // 0..15
    const int tn = tid & 15;       // 0..15

    __shared__ float As[32][68];   // [k][b]
    __shared__ float Ws[32][68];   // [k][n]

    float acc[4][4] = {};

    const float* Ag = Aroot + (AHASC ? (size_t)c * Bn * K : 0) + (size_t)b0 * K;
    const float* Wg = W + (size_t)c * K * N + n0;

    const int arow = tid >> 2;          // 0..63
    const int acol = (tid & 3) * 8;     // 0..24
    const int wrow = tid >> 3;          // 0..31
    const int wcol = (tid & 7) * 8;     // 0..56

    // prologue: prefetch tile 0 into registers
    float4 a0 = *(const float4*)(Ag + (size_t)arow * K + acol);
    float4 a1 = *(const float4*)(Ag + (size_t)arow * K + acol + 4);
    float4 w0 = *(const float4*)(Wg + (size_t)wrow * N + wcol);
    float4 w1 = *(const float4*)(Wg + (size_t)wrow * N + wcol + 4);

    for (int k0 = 0; k0 < K; k0 += 32) {
        __syncthreads();  // previous tile fully consumed
        As[acol + 0][arow] = a0.x; As[acol + 1][arow] = a0.y;
        As[acol + 2][arow] = a0.z; As[acol + 3][arow] = a0.w;
        As[acol + 4][arow] = a1.x; As[acol + 5][arow] = a1.y;
        As[acol + 6][arow] = a1.z; As[acol + 7][arow] = a1.w;
        *(float4*)&Ws[wrow][wcol]     = w0;
        *(float4*)&Ws[wrow][wcol + 4] = w1;
        __syncthreads();

        if (k0 + 32 < K) {  // prefetch next tile; latency hidden by compute
            a0 = *(const float4*)(Ag + (size_t)arow * K + k0 + 32 + acol);
            a1 = *(const float4*)(Ag + (size_t)arow * K + k0 + 32 + acol + 4);
            w0 = *(const float4*)(Wg + (size_t)(k0 + 32 + wrow) * N + wcol);
            w1 = *(const float4*)(Wg + (size_t)(k0 + 32 + wrow) * N + wcol + 4);
        }

#pragma unroll
        for (int k = 0; k < 32; k++) {
            float4 av = *(const float4*)&As[k][tb * 4];
            float4 wv = *(const float4*)&Ws[k][tn * 4];
            float a[4] = {av.x, av.y, av.z, av.w};
            float w[4] = {wv.x, wv.y, wv.z, wv.w};
#pragma unroll
            for (int i = 0; i < 4; i++)
#pragma unroll
                for (int j = 0; j < 4; j++)
                    acc[i][j] = fmaf(a[i], w[j], acc[i][j]);
        }
    }

    const float* bptr = bias + c * N + n0 + tn * 4;
    float bx = bptr[0], by = bptr[1], bz = bptr[2], bw = bptr[3];
#pragma unroll
    for (int i = 0; i < 4; i++) {
        const int b = b0 + tb * 4 + i;
        float4 o;
        o.x = fmaxf(acc[i][0] + bx, 0.0f);
        o.y = fmaxf(acc[i][1] + by, 0.0f);
        o.z = fmaxf(acc[i][2] + bz, 0.0f);
        o.w = fmaxf(acc[i][3] + bw, 0.0f);
        *(float4*)(Oroot + ((size_t)(c * Bn + b)) * N + n0 + tn * 4) = o;
    }
}

// ---------------------------------------------------------------------------
// 3) Layer 3 fused with L2 normalize. Tile 16(b) x 128(n, full row), K=256.
// ---------------------------------------------------------------------------
__global__ __launch_bounds__(128) void gemm3_norm_kernel(
        const float* __restrict__ W, const float* __restrict__ bias,
        float* __restrict__ zout) {
    constexpr int K = U2;   // 256
    constexpr int N = U3;   // 128
    const int b0 = blockIdx.x * 16;
    const int c  = blockIdx.y;
    const int tid = threadIdx.x;
    const int w = tid >> 5;
    const int lane = tid & 31;

    __shared__ float As[32][20];    // [k][b]
    __shared__ float Ws[32][128];   // [k][n]

    float acc[4][4] = {};

    const float* Ag = g_h2 + (size_t)c * Bn * K + (size_t)b0 * K;
    const float* Wg = W + (size_t)c * K * N;

    const int arow = tid >> 3;       // 0..15
    const int acol = (tid & 7) * 4;  // 0..28

    // prologue prefetch
    float4 areg = *(const float4*)(Ag + (size_t)arow * K + acol);
    float4 wreg[8];
#pragma unroll
    for (int it = 0; it < 8; it++) {
        const int f = it * 128 + tid;
        const int row = f >> 5, c4 = f & 31;
        wreg[it] = *(const float4*)(Wg + (size_t)row * N + c4 * 4);
    }

    for (int k0 = 0; k0 < K; k0 += 32) {
        __syncthreads();
        As[acol + 0][arow] = areg.x; As[acol + 1][arow] = areg.y;
        As[acol + 2][arow] = areg.z; As[acol + 3][arow] = areg.w;
#pragma unroll
        for (int it = 0; it < 8; it++) {
            const int f = it * 128 + tid;
            const int row = f >> 5, c4 = f & 31;
            *(float4*)&Ws[row][c4 * 4] = wreg[it];
        }
        __syncthreads();

        if (k0 + 32 < K) {
            areg = *(const float4*)(Ag + (size_t)arow * K + k0 + 32 + acol);
#pragma unroll
            for (int it = 0; it < 8; it++) {
                const int f = it * 128 + tid;
                const int row = f >> 5, c4 = f & 31;
                wreg[it] = *(const float4*)(Wg + (size_t)(k0 + 32 + row) * N + c4 * 4);
            }
        }

#pragma unroll
        for (int k = 0; k < 32; k++) {
            float4 av = *(const float4*)&As[k][w * 4];      // warp broadcast
            float4 wv = *(const float4*)&Ws[k][lane * 4];
            float a[4] = {av.x, av.y, av.z, av.w};
            float ww[4] = {wv.x, wv.y, wv.z, wv.w};
#pragma unroll
            for (int i = 0; i < 4; i++)
#pragma unroll
                for (int j = 0; j < 4; j++)
                    acc[i][j] = fmaf(a[i], ww[j], acc[i][j]);
        }
    }

    const float* bptr = bias + c * N + lane * 4;
    float bx = bptr[0], by = bptr[1], bz = bptr[2], bw = bptr[3];
#pragma unroll
    for (int i = 0; i < 4; i++) {
        float h0 = fmaxf(acc[i][0] + bx, 0.0f);
        float h1 = fmaxf(acc[i][1] + by, 0.0f);
        float h2 = fmaxf(acc[i][2] + bz, 0.0f);
        float h3 = fmaxf(acc[i][3] + bw, 0.0f);
        float ssq = h0 * h0 + h1 * h1 + h2 * h2 + h3 * h3;
#pragma unroll
        for (int o = 16; o; o >>= 1) ssq += __shfl_xor_sync(0xffffffffu, ssq, o);
        const float r = rsqrtf(fmaxf(ssq, 1e-12f));
        float4 o4 = {h0 * r, h1 * r, h2 * r, h3 * r};
        *(float4*)(zout + ((size_t)(c * Bn + b0 + w * 4 + i)) * N + lane * 4) = o4;
    }
}

// ---------------------------------------------------------------------------
// 4) Per-(c,b) contrastive term. grid (C, 8); 256 threads = 8 warps,
//    4 rows per warp.
// ---------------------------------------------------------------------------
#define ZPAD 132
__global__ __launch_bounds__(256) void loss_kernel(const float* __restrict__ z,
                                                   const int* __restrict__ label) {
    extern __shared__ float zs[];          // [256][ZPAD]
    __shared__ int slab[Bn];
    __shared__ int s_nump;

    const int c = blockIdx.x;
    const int tid = threadIdx.x;
    const int lane = tid & 31;
    const int warp = tid >> 5;

    const float* zc = z + (size_t)c * Bn * U3;
    for (int idx = tid; idx < Bn * U3 / 4; idx += 256) {
        const int row = idx >> 5;
        const int c4 = idx & 31;
        float4 v = *(const float4*)(zc + (size_t)row * U3 + c4 * 4);
        *(float4*)&zs[row * ZPAD + c4 * 4] = v;
    }
    slab[tid] = label[tid * Cn + c];
    __syncthreads();
    if (tid == 0) {
        int s = 0;
        for (int i = 0; i < Bn; i++) s += slab[i];
        s_nump = s;
    }
    __syncthreads();

    const int bb = blockIdx.y * 32 + warp * 4;   // 4 rows per warp
    const int nump = s_nump;

    int lb[4];
    const float* zb[4];
#pragma unroll
    for (int i = 0; i < 4; i++) {
        lb[i] = slab[bb + i];
        zb[i] = &zs[(bb + i) * ZPAD];
    }

    float es[4] = {0.f, 0.f, 0.f, 0.f};
    float ps[4] = {0.f, 0.f, 0.f, 0.f};

#pragma unroll
    for (int kk = 0; kk < 8; kk++) {
        const int k = kk * 32 + lane;
        const float* zk = &zs[k * ZPAD];
        float s0 = 0.f, s1 = 0.f, s2 = 0.f, s3 = 0.f;
#pragma unroll
        for (int j = 0; j < U3; j += 4) {
            float4 x = *(const float4*)(zk + j);
            float4 a0 = *(const float4*)(zb[0] + j);
            float4 a1 = *(const float4*)(zb[1] + j);
            float4 a2 = *(const float4*)(zb[2] + j);
            float4 a3 = *(const float4*)(zb[3] + j);
            s0 = fmaf(a0.x, x.x, s0); s0 = fmaf(a0.y, x.y, s0);
            s0 = fmaf(a0.z, x.z, s0); s0 = fmaf(a0.w, x.w, s0);
            s1 = fmaf(a1.x, x.x, s1); s1 = fmaf(a1.y, x.y, s1);
            s1 = fmaf(a1.z, x.z, s1); s1 = fmaf(a1.w, x.w, s1);
            s2 = fmaf(a2.x, x.x, s2); s2 = fmaf(a2.y, x.y, s2);
            s2 = fmaf(a2.z, x.z, s2); s2 = fmaf(a2.w, x.w, s2);
            s3 = fmaf(a3.x, x.x, s3); s3 = fmaf(a3.y, x.y, s3);
            s3 = fmaf(a3.z, x.z, s3); s3 = fmaf(a3.w, x.w, s3);
        }
        const int sk = slab[k];
        float sv[4] = {s0, s1, s2, s3};
#pragma unroll
        for (int i = 0; i < 4; i++) {
            const float ipv = (k == bb + i) ? 0.0f : sv[i] * 2.0f;  // /TEMP
            es[i] += __expf(ipv);
            if (sk == lb[i]) ps[i] += ipv;
        }
    }

#pragma unroll
    for (int i = 0; i < 4; i++) {
#pragma unroll
        for (int o = 16; o; o >>= 1) {
            es[i] += __shfl_xor_sync(0xffffffffu, es[i], o);
            ps[i] += __shfl_xor_sync(0xffffffffu, ps[i], o);
        }
    }
    if (lane == 0) {
#pragma unroll
        for (int i = 0; i < 4; i++) {
            const int numv = lb[i] ? nump : (Bn - nump);
            g_term[c * Bn + bb + i] = ps[i] / (float)numv - logf(es[i]);
        }
    }
}

// ---------------------------------------------------------------------------
// 5) Reduce terms -> losses[c]
// ---------------------------------------------------------------------------
__global__ void final_kernel(float* __restrict__ out) {
    __shared__ float red[Bn];
    const int c = blockIdx.x;
    const int tid = threadIdx.x;
    red[tid] = g_term[c * Bn + tid];
    __syncthreads();
    for (int s = 128; s; s >>= 1) {
        if (tid < s) red[tid] += red[tid + s];
        __syncthreads();
    }
    if (tid == 0) out[(size_t)Cn * Bn * U3 + c] = -red[0];
}

// ---------------------------------------------------------------------------
extern "C" void kernel_launch(void* const* d_in, const int* in_sizes, int n_in,
                              void* d_out, int out_size) {
    const float* ec    = (const float*)d_in[0];
    const float* mask  = (const float*)d_in[1];
    const int*   label = (const int*)d_in[2];
    const float* W1    = (const float*)d_in[3];
    const float* b1    = (const float*)d_in[4];
    const float* W2    = (const float*)d_in[5];
    const float* b2    = (const float*)d_in[6];
    const float* W3    = (const float*)d_in[7];
    const float* b3    = (const float*)d_in[8];
    float* out = (float*)d_out;

    const int loss_smem = Bn * ZPAD * (int)sizeof(float);
    cudaFuncSetAttribute(loss_kernel,
                         cudaFuncAttributeMaxDynamicSharedMemorySize, loss_smem);

    pool_kernel<<<dim3(Bn, 2), 256>>>(ec, mask);
    gemm_relu_kernel<1><<<dim3(U1 / 64, Bn / 64, Cn), 256>>>(W1, b1);
    gemm_relu_kernel<2><<<dim3(U2 / 64, Bn / 64, Cn), 256>>>(W2, b2);
    gemm3_norm_kernel<<<dim3(Bn / 16, Cn), 128>>>(W3, b3, out);
    loss_kernel<<<dim3(Cn, Bn / 32), 256, loss_smem>>>(out, label);
    final_kernel<<<Cn, Bn>>>(out);
}